// round 10
// baseline (speedup 1.0000x reference)
#include <cuda_runtime.h>
#include <math.h>
#include <stdint.h>

#define Nn 8192
#define Dd 256

typedef unsigned long long ull;

// ---------------- scratch (device globals; no allocation allowed) ----------------
__device__ float g_Hn[Nn * Dd];     // batch-normed H
__device__ float g_F1[Nn * Dd];     // theta projection -> normalized rows (in place)
__device__ float g_Y[Nn * Dd];      // Hn @ W_out + b_out
__device__ float g_part[2 * 64 * Dd];
__device__ float g_mu[Dd], g_rstd[Dd];
__device__ float g_tval[Nn * 5];
__device__ int   g_tidx[Nn * 5];
__device__ float g_dinv[Nn];

// ---------------- K1a: per-column partial sums over row slices ----------------
__global__ void bn_partial(const float* __restrict__ H) {
    int col = threadIdx.x;                // 256 threads = 256 columns (coalesced)
    int r0 = blockIdx.x * 128;
    float s = 0.f, s2 = 0.f;
    for (int r = 0; r < 128; ++r) {
        float v = H[(size_t)(r0 + r) * Dd + col];
        s += v; s2 += v * v;
    }
    g_part[blockIdx.x * Dd + col] = s;
    g_part[64 * Dd + blockIdx.x * Dd + col] = s2;
}

// ---------------- K1b: finish mean / rstd ----------------
__global__ void bn_finish() {
    int col = threadIdx.x;
    float s = 0.f, s2 = 0.f;
    for (int b = 0; b < 64; ++b) {
        s  += g_part[b * Dd + col];
        s2 += g_part[64 * Dd + b * Dd + col];
    }
    float mu  = s  / (float)Nn;
    float var = s2 / (float)Nn - mu * mu;
    g_mu[col] = mu;
    g_rstd[col] = __frsqrt_rn(var + 1e-5f);
}

// ---------------- K2: apply BN ----------------
__global__ void bn_apply(const float* __restrict__ H,
                         const float* __restrict__ gamma,
                         const float* __restrict__ beta) {
    int idx = blockIdx.x * 256 + threadIdx.x;
    int col = idx & (Dd - 1);
    float v = H[idx];
    g_Hn[idx] = (v - g_mu[col]) * g_rstd[col] * gamma[col] + beta[col];
}

// ---------------- K3: C[8192,256] = Hn @ W + bias (templated destination) ----------------
template <int WHICH>  // 0 -> g_F1 (theta), 1 -> g_Y (out proj)
__global__ __launch_bounds__(256) void gemm_bias(const float* __restrict__ W,
                                                 const float* __restrict__ bias) {
    const int BM = 64, BN = 64, BK = 16;
    __shared__ float As[BK][BM + 4];
    __shared__ float Bs[BK][BN];
    int tid = threadIdx.x;
    int tx = tid & 15, ty = tid >> 4;
    int m0 = blockIdx.x * BM, n0 = blockIdx.y * BN;
    float acc[4][4] = {};
    for (int k0 = 0; k0 < Dd; k0 += BK) {
        __syncthreads();
        int lk = tid & 15, lmb = tid >> 4;
        #pragma unroll
        for (int s = 0; s < 4; ++s) {
            int lm = lmb + s * 16;
            As[lk][lm] = g_Hn[(size_t)(m0 + lm) * Dd + k0 + lk];
        }
        int ln = tid & 63, lkb = tid >> 6;
        #pragma unroll
        for (int s = 0; s < 4; ++s) {
            int lk2 = lkb + s * 4;
            Bs[lk2][ln] = W[(size_t)(k0 + lk2) * Dd + n0 + ln];
        }
        __syncthreads();
        #pragma unroll
        for (int k = 0; k < BK; ++k) {
            float a[4], b[4];
            #pragma unroll
            for (int i = 0; i < 4; ++i) a[i] = As[k][ty * 4 + i];
            #pragma unroll
            for (int j = 0; j < 4; ++j) b[j] = Bs[k][tx * 4 + j];
            #pragma unroll
            for (int i = 0; i < 4; ++i)
                #pragma unroll
                for (int j = 0; j < 4; ++j)
                    acc[i][j] += a[i] * b[j];
        }
    }
    float* C = (WHICH == 0) ? g_F1 : g_Y;
    #pragma unroll
    for (int i = 0; i < 4; ++i)
        #pragma unroll
        for (int j = 0; j < 4; ++j)
            C[(size_t)(m0 + ty * 4 + i) * Dd + n0 + tx * 4 + j] =
                acc[i][j] + bias[n0 + tx * 4 + j];
}

// ---------------- K4: row-normalize g_F1 in place (one warp per row) ----------------
__global__ void rownorm() {
    int w = threadIdx.x >> 5, lane = threadIdx.x & 31;
    int row = blockIdx.x * 8 + w;
    float v[8]; float ss = 0.f;
    #pragma unroll
    for (int s = 0; s < 8; ++s) {
        v[s] = g_F1[(size_t)row * Dd + lane + 32 * s];
        ss += v[s] * v[s];
    }
    #pragma unroll
    for (int o = 16; o; o >>= 1) ss += __shfl_xor_sync(0xffffffffu, ss, o);
    float nrm = fmaxf(__fsqrt_rn(ss), 1e-12f);
    #pragma unroll
    for (int s = 0; s < 8; ++s)
        g_F1[(size_t)row * Dd + lane + 32 * s] = __fdiv_rn(v[s], nrm);
}

// ---------------- K5: fused similarity GEMM (f32x2) + per-row top-k ----------------
// Hot loop selects top-8 candidates by RAW dot product d (no transcendentals).
// Final ranking recomputes A = affinity(d) for those 8 and picks top-5 by
// (A desc, index asc) — the exact comparator the reference's top_k uses.
// The 3-candidate margin absorbs fp non-monotonicity of acosf/expf and
// equal-A ties; discrepancies only occur within ~1e-6-wide d windows.
#define TMr 32
#define TNc 256
#define TKK 16

__device__ __forceinline__ float affinity(float d) {
    d = fminf(1.0f, fmaxf(-1.0f, d));            // clip
    float s = acosf(d);                           // SAM angle
    float e = expf(-0.2f * s);
    float A = __fdiv_rn(1.0f, 1.0f + expf(-e));   // sigmoid
    return fmaxf(A, 0.1f);                        // clamp (never binds; fidelity)
}

__device__ __forceinline__ ull splat2(float a) {
    ull r;
    unsigned int u = __float_as_uint(a);
    asm("mov.b64 %0, {%1, %1};" : "=l"(r) : "r"(u));
    return r;
}
__device__ __forceinline__ void ffma2(ull& d, ull a, ull b) {
    asm("fma.rn.f32x2 %0, %1, %2, %3;" : "=l"(d) : "l"(a), "l"(b), "l"(d));
}
__device__ __forceinline__ void unpack2(ull p, float& lo, float& hi) {
    unsigned int l, h;
    asm("mov.b64 {%0, %1}, %2;" : "=r"(l), "=r"(h) : "l"(p));
    lo = __uint_as_float(l); hi = __uint_as_float(h);
}

__global__ __launch_bounds__(256, 2) void topk_kernel() {
    __shared__ float As[TKK][TMr + 4];    // stride 36 floats (144B, 16B-aligned rows)
    __shared__ float Bs[TKK][TNc + 2];    // stride 258 floats (even -> 8B pair alignment)

    int tx = threadIdx.x;                 // 0..31 (lane)
    int ty = threadIdx.y;                 // 0..7  (warp id)
    int tid = ty * 32 + tx;
    int rowBase = blockIdx.x * TMr;

    // per-thread top-5 of raw dot product, rows rowBase + ty*4 + i
    float dv[4][5];
    int   di[4][5];
    #pragma unroll
    for (int i = 0; i < 4; ++i)
        #pragma unroll
        for (int q = 0; q < 5; ++q) { dv[i][q] = -2.0f; di[i][q] = 0x7fffffff; }

    for (int jt = 0; jt < Nn; jt += TNc) {
        ull acc[4][4];
        #pragma unroll
        for (int i = 0; i < 4; ++i)
            #pragma unroll
            for (int p = 0; p < 4; ++p) acc[i][p] = 0ull;

        for (int k0 = 0; k0 < Dd; k0 += TKK) {
            __syncthreads();
            // load A tile: 32 rows x 16 k
            #pragma unroll
            for (int s = 0; s < 2; ++s) {
                int idx = tid + 256 * s;
                int m = idx >> 4, lk = idx & 15;
                As[lk][m] = g_F1[(size_t)(rowBase + m) * Dd + k0 + lk];
            }
            // load B tile: 256 cols x 16 k (STS conflict-free: stride 258 == 2 mod 32)
            #pragma unroll
            for (int s = 0; s < 16; ++s) {
                int idx = tid + 256 * s;
                int c = idx >> 4, lk = idx & 15;
                Bs[lk][c] = g_F1[(size_t)(jt + c) * Dd + k0 + lk];
            }
            __syncthreads();
            #pragma unroll
            for (int k = 0; k < TKK; ++k) {
                float4 a4 = *reinterpret_cast<const float4*>(&As[k][ty * 4]); // broadcast
                ull a2[4];
                a2[0] = splat2(a4.x); a2[1] = splat2(a4.y);
                a2[2] = splat2(a4.z); a2[3] = splat2(a4.w);
                ull b[4];
                #pragma unroll
                for (int p = 0; p < 4; ++p)
                    b[p] = *reinterpret_cast<const ull*>(&Bs[k][64 * p + 2 * tx]);
                #pragma unroll
                for (int i = 0; i < 4; ++i)
                    #pragma unroll
                    for (int p = 0; p < 4; ++p)
                        ffma2(acc[i][p], a2[i], b[p]);
            }
        }
        // epilogue: insert raw dots into per-row top-5 (ascending j => stable ties)
        #pragma unroll
        for (int p = 0; p < 4; ++p) {
            int j0 = jt + 64 * p + 2 * tx;
            #pragma unroll
            for (int i = 0; i < 4; ++i) {
                float dlo, dhi;
                unpack2(acc[i][p], dlo, dhi);
                #pragma unroll
                for (int e = 0; e < 2; ++e) {
                    float d = (e == 0) ? dlo : dhi;
                    int j = j0 + e;
                    if (d > dv[i][4]) {
                        dv[i][4] = d; di[i][4] = j;
                        #pragma unroll
                        for (int m2 = 3; m2 >= 0; --m2) {
                            if (dv[i][m2 + 1] > dv[i][m2]) {
                                float tv = dv[i][m2]; dv[i][m2] = dv[i][m2 + 1]; dv[i][m2 + 1] = tv;
                                int ti = di[i][m2]; di[i][m2] = di[i][m2 + 1]; di[i][m2 + 1] = ti;
                            }
                        }
                    }
                }
            }
        }
    }

    // warp-level merge: 32 sorted 5-lists -> global top-8 by d per row
    // (tie on d: lowest index). Then re-rank those 8 in A-space.
    #pragma unroll
    for (int i = 0; i < 4; ++i) {
        int pos = 0;
        float wv[8]; int wi[8];
        #pragma unroll
        for (int sel = 0; sel < 8; ++sel) {
            float cv = (pos < 5) ? dv[i][pos] : -3.0f;
            int   ci = (pos < 5) ? di[i][pos] : 0x7fffffff;
            #pragma unroll
            for (int o = 16; o; o >>= 1) {
                float ov = __shfl_xor_sync(0xffffffffu, cv, o);
                int   oi = __shfl_xor_sync(0xffffffffu, ci, o);
                if (ov > cv || (ov == cv && oi < ci)) { cv = ov; ci = oi; }
            }
            wv[sel] = cv; wi[sel] = ci;
            if (pos < 5 && di[i][pos] == ci) ++pos;   // column indices are unique
        }
        if (tx == 0) {
            // Recompute A for the 8 candidates; select top-5 by (A desc, idx asc)
            // — the reference's exact comparator (jax.lax.top_k on A, stable).
            float av8[8];
            #pragma unroll
            for (int q = 0; q < 8; ++q) av8[q] = affinity(wv[q]);
            bool used[8] = {false, false, false, false, false, false, false, false};
            float fv[5]; int fi[5];
            #pragma unroll
            for (int sel = 0; sel < 5; ++sel) {
                float best = -1e30f; int bidx = 0x7fffffff; int bpos = -1;
                #pragma unroll
                for (int p = 0; p < 8; ++p) {
                    if (!used[p] &&
                        (av8[p] > best || (av8[p] == best && wi[p] < bidx))) {
                        best = av8[p]; bidx = wi[p]; bpos = p;
                    }
                }
                used[bpos] = true; fv[sel] = best; fi[sel] = bidx;
            }
            // sort kept entries by ascending column index (matches jax's sum order)
            #pragma unroll
            for (int a = 0; a < 4; ++a)
                #pragma unroll
                for (int b2 = 0; b2 < 4 - a; ++b2)
                    if (fi[b2] > fi[b2 + 1]) {
                        int ti = fi[b2]; fi[b2] = fi[b2 + 1]; fi[b2 + 1] = ti;
                        float tv = fv[b2]; fv[b2] = fv[b2 + 1]; fv[b2 + 1] = tv;
                    }
            float sum = 0.f;
            #pragma unroll
            for (int q = 0; q < 5; ++q) sum += fv[q];
            int gr = rowBase + ty * 4 + i;
            #pragma unroll
            for (int q = 0; q < 5; ++q) { g_tval[gr * 5 + q] = fv[q]; g_tidx[gr * 5 + q] = fi[q]; }
            g_dinv[gr] = __fdiv_rn(1.0f, __fsqrt_rn(sum));
        }
    }
}

// ---------------- K6: zero + scatter masked A (one block per row) ----------------
__global__ void writeA(float* __restrict__ Aout) {
    int row = blockIdx.x;
    float4* rp = reinterpret_cast<float4*>(Aout + (size_t)row * Nn);
    float4 z = make_float4(0.f, 0.f, 0.f, 0.f);
    #pragma unroll
    for (int s = 0; s < 8; ++s) rp[threadIdx.x + 256 * s] = z;
    __syncthreads();
    if (threadIdx.x < 5) {
        int j = g_tidx[row * 5 + threadIdx.x];
        Aout[(size_t)row * Nn + j] = g_tval[row * 5 + threadIdx.x];
    }
}

// ---------------- K7: out = A_hat @ Y, LeakyReLU (one block per row) ----------------
__global__ void out_gemm(float* __restrict__ Out) {
    __shared__ float sw[5];
    __shared__ int sj[5];
    int row = blockIdx.x;
    if (threadIdx.x < 5) {
        int j = g_tidx[row * 5 + threadIdx.x];
        sj[threadIdx.x] = j;
        sw[threadIdx.x] = (g_dinv[row] * g_tval[row * 5 + threadIdx.x]) * g_dinv[j];
    }
    __syncthreads();
    int c = threadIdx.x;
    float acc = 0.f;
    #pragma unroll
    for (int q = 0; q < 5; ++q)
        acc += sw[q] * g_Y[(size_t)sj[q] * Dd + c];
    Out[(size_t)row * Dd + c] = (acc >= 0.f) ? acc : 0.01f * acc;
}

// ---------------- launcher ----------------
extern "C" void kernel_launch(void* const* d_in, const int* in_sizes, int n_in,
                              void* d_out, int out_size) {
    (void)in_sizes; (void)n_in;
    const float* H     = (const float*)d_in[0];
    const float* gamma = (const float*)d_in[1];
    const float* beta  = (const float*)d_in[2];
    const float* Wt    = (const float*)d_in[3];
    const float* bt    = (const float*)d_in[4];
    const float* Wo    = (const float*)d_in[5];
    const float* bo    = (const float*)d_in[6];
    float* outp = (float*)d_out;

    bn_partial<<<64, 256>>>(H);
    bn_finish<<<1, 256>>>();
    bn_apply<<<(Nn * Dd) / 256, 256>>>(H, gamma, beta);
    gemm_bias<0><<<dim3(Nn / 64, Dd / 64), 256>>>(Wt, bt);   // g_F1 = Hn@Wt + bt
    gemm_bias<1><<<dim3(Nn / 64, Dd / 64), 256>>>(Wo, bo);   // g_Y  = Hn@Wo + bo
    rownorm<<<Nn / 8, 256>>>();
    {
        dim3 blk(32, 8, 1);
        topk_kernel<<<Nn / TMr, blk>>>();
    }

    long long need_both = (long long)Nn * Dd + (long long)Nn * Nn;
    if ((long long)out_size >= need_both)
        writeA<<<Nn, 256>>>(outp + (size_t)Nn * Dd);
    out_gemm<<<Nn, 256>>>(outp);
}

// round 11
// speedup vs baseline: 5.7931x; 5.7931x over previous
#include <cuda_runtime.h>
#include <cuda_bf16.h>
#include <math.h>
#include <stdint.h>

#define Nn 8192
#define Dd 256

typedef unsigned long long ull;

// ---------------- scratch (device globals; no allocation allowed) ----------------
__device__ float g_Hn[Nn * Dd];
__device__ float g_F1[Nn * Dd];
__device__ float g_Y[Nn * Dd];
__device__ __nv_bfloat16 g_F1h[Nn * Dd];
__device__ __nv_bfloat16 g_F1l[Nn * Dd];
__device__ float g_part[2 * 64 * Dd];
__device__ float g_mu[Dd], g_rstd[Dd];
__device__ float g_tval[Nn * 5];
__device__ int   g_tidx[Nn * 5];
__device__ float g_dinv[Nn];

// ---------------- K1a: per-column partial sums ----------------
__global__ void bn_partial(const float* __restrict__ H) {
    int col = threadIdx.x;
    int r0 = blockIdx.x * 128;
    float s = 0.f, s2 = 0.f;
    for (int r = 0; r < 128; ++r) {
        float v = H[(size_t)(r0 + r) * Dd + col];
        s += v; s2 += v * v;
    }
    g_part[blockIdx.x * Dd + col] = s;
    g_part[64 * Dd + blockIdx.x * Dd + col] = s2;
}

__global__ void bn_finish() {
    int col = threadIdx.x;
    float s = 0.f, s2 = 0.f;
    for (int b = 0; b < 64; ++b) {
        s  += g_part[b * Dd + col];
        s2 += g_part[64 * Dd + b * Dd + col];
    }
    float mu  = s  / (float)Nn;
    float var = s2 / (float)Nn - mu * mu;
    g_mu[col] = mu;
    g_rstd[col] = __frsqrt_rn(var + 1e-5f);
}

__global__ void bn_apply(const float* __restrict__ H,
                         const float* __restrict__ gamma,
                         const float* __restrict__ beta) {
    int idx = blockIdx.x * 256 + threadIdx.x;
    int col = idx & (Dd - 1);
    float v = H[idx];
    g_Hn[idx] = (v - g_mu[col]) * g_rstd[col] * gamma[col] + beta[col];
}

// ---------------- K3: C = Hn @ W + bias ----------------
template <int WHICH>
__global__ __launch_bounds__(256) void gemm_bias(const float* __restrict__ W,
                                                 const float* __restrict__ bias) {
    const int BM = 64, BN = 64, BK = 16;
    __shared__ float As[BK][BM + 4];
    __shared__ float Bs[BK][BN];
    int tid = threadIdx.x;
    int tx = tid & 15, ty = tid >> 4;
    int m0 = blockIdx.x * BM, n0 = blockIdx.y * BN;
    float acc[4][4] = {};
    for (int k0 = 0; k0 < Dd; k0 += BK) {
        __syncthreads();
        int lk = tid & 15, lmb = tid >> 4;
        #pragma unroll
        for (int s = 0; s < 4; ++s) {
            int lm = lmb + s * 16;
            As[lk][lm] = g_Hn[(size_t)(m0 + lm) * Dd + k0 + lk];
        }
        int ln = tid & 63, lkb = tid >> 6;
        #pragma unroll
        for (int s = 0; s < 4; ++s) {
            int lk2 = lkb + s * 4;
            Bs[lk2][ln] = W[(size_t)(k0 + lk2) * Dd + n0 + ln];
        }
        __syncthreads();
        #pragma unroll
        for (int k = 0; k < BK; ++k) {
            float a[4], b[4];
            #pragma unroll
            for (int i = 0; i < 4; ++i) a[i] = As[k][ty * 4 + i];
            #pragma unroll
            for (int j = 0; j < 4; ++j) b[j] = Bs[k][tx * 4 + j];
            #pragma unroll
            for (int i = 0; i < 4; ++i)
                #pragma unroll
                for (int j = 0; j < 4; ++j)
                    acc[i][j] += a[i] * b[j];
        }
    }
    float* C = (WHICH == 0) ? g_F1 : g_Y;
    #pragma unroll
    for (int i = 0; i < 4; ++i)
        #pragma unroll
        for (int j = 0; j < 4; ++j)
            C[(size_t)(m0 + ty * 4 + i) * Dd + n0 + tx * 4 + j] =
                acc[i][j] + bias[n0 + tx * 4 + j];
}

// ---------------- K4: row-normalize g_F1 ----------------
__global__ void rownorm() {
    int w = threadIdx.x >> 5, lane = threadIdx.x & 31;
    int row = blockIdx.x * 8 + w;
    float v[8]; float ss = 0.f;
    #pragma unroll
    for (int s = 0; s < 8; ++s) {
        v[s] = g_F1[(size_t)row * Dd + lane + 32 * s];
        ss += v[s] * v[s];
    }
    #pragma unroll
    for (int o = 16; o; o >>= 1) ss += __shfl_xor_sync(0xffffffffu, ss, o);
    float nrm = fmaxf(__fsqrt_rn(ss), 1e-12f);
    #pragma unroll
    for (int s = 0; s < 8; ++s)
        g_F1[(size_t)row * Dd + lane + 32 * s] = __fdiv_rn(v[s], nrm);
}

// ---------------- K4b: split F1 into bf16 hi + lo ----------------
__global__ void split_bf16() {
    int idx = blockIdx.x * 256 + threadIdx.x;
    float f = g_F1[idx];
    __nv_bfloat16 hi = __float2bfloat16(f);
    float r = f - __bfloat162float(hi);
    g_F1h[idx] = hi;
    g_F1l[idx] = __float2bfloat16(r);
}

// ---------------- K5: similarity via bf16-split mma.sync + top-k ----------------
// d~ = hi.hi^T + hi.lo^T + lo.hi^T (fp32 accum). Select per-row top-8 by d~,
// re-rank those 8 with A = affinity(d) under (A desc, idx asc) — reference's
// exact comparator — keep 5.
#define ASTRIDE_B 528          // bytes per A smem row (264 bf16)
#define BSTRIDE_B 144          // bytes per B smem row (72 bf16)
#define KC 64                  // k-chunk
#define A_HI_OFF 0
#define A_LO_OFF 33792         // 64*528
#define B_OFF 67584
#define B_SEG 18432            // 128*144
#define SMEM_TOTAL_TOPK 141312 // B_OFF + 4*B_SEG

__device__ __forceinline__ float affinity(float d) {
    d = fminf(1.0f, fmaxf(-1.0f, d));
    float s = acosf(d);
    float e = expf(-0.2f * s);
    float A = __fdiv_rn(1.0f, 1.0f + expf(-e));
    return fmaxf(A, 0.1f);
}

__device__ __forceinline__ void ldsm4(unsigned* r, uint32_t addr) {
    asm volatile("ldmatrix.sync.aligned.m8n8.x4.shared.b16 {%0,%1,%2,%3},[%4];"
                 : "=r"(r[0]), "=r"(r[1]), "=r"(r[2]), "=r"(r[3]) : "r"(addr));
}
__device__ __forceinline__ void mma16816(float* c, const unsigned* a,
                                         unsigned b0, unsigned b1) {
    asm volatile(
        "mma.sync.aligned.m16n8k16.row.col.f32.bf16.bf16.f32 "
        "{%0,%1,%2,%3},{%4,%5,%6,%7},{%8,%9},{%0,%1,%2,%3};"
        : "+f"(c[0]), "+f"(c[1]), "+f"(c[2]), "+f"(c[3])
        : "r"(a[0]), "r"(a[1]), "r"(a[2]), "r"(a[3]), "r"(b0), "r"(b1));
}
__device__ __forceinline__ void cp16(uint32_t saddr, const void* gptr) {
    asm volatile("cp.async.cg.shared.global [%0], [%1], 16;"
                 :: "r"(saddr), "l"(__cvta_generic_to_global(gptr)));
}

__global__ __launch_bounds__(256, 1) void topk_mma() {
    extern __shared__ char sm[];
    uint32_t smb = (uint32_t)__cvta_generic_to_shared(sm);

    int tid = threadIdx.x;
    int lane = tid & 31, warp = tid >> 5;
    int warp_m = warp & 3, warp_n = warp >> 2;
    int rowBase = blockIdx.x * 64;

    // ---- load persistent A tile: 64 rows x 256 k (hi & lo) ----
    for (int idx = tid; idx < 64 * 32; idx += 256) {
        int row = idx >> 5, seg = idx & 31;
        const uint4* gh = (const uint4*)(g_F1h + (size_t)(rowBase + row) * Dd + seg * 8);
        const uint4* gl = (const uint4*)(g_F1l + (size_t)(rowBase + row) * Dd + seg * 8);
        *(uint4*)(sm + A_HI_OFF + row * ASTRIDE_B + seg * 16) = *gh;
        *(uint4*)(sm + A_LO_OFF + row * ASTRIDE_B + seg * 16) = *gl;
    }
    __syncthreads();

    // per-thread top-5 (by raw d) for rows r1, r2
    float dv[2][5]; int di[2][5];
    #pragma unroll
    for (int r = 0; r < 2; ++r)
        #pragma unroll
        for (int q = 0; q < 5; ++q) { dv[r][q] = -2.0f; di[r][q] = 0x7fffffff; }

    float acc[8][4];

    // ldmatrix lane addressing
    int aRow = warp_m * 16 + (lane & 15);
    uint32_t aAddrBase = smb + aRow * ASTRIDE_B + (lane >> 4) * 16;
    int bColLane = (lane & 15);
    uint32_t bAddrLane = (uint32_t)((warp_n * 64 + bColLane) * BSTRIDE_B + (lane >> 4) * 16);

    // prefetch chunk 0
    {
        int jt = 0, kcc = 0, buf = 0;
        for (int i = tid; i < 1024; i += 256) {
            int col = i >> 3, seg = i & 7;
            size_t go = (size_t)(jt * 128 + col) * Dd + kcc + seg * 8;
            uint32_t so = B_OFF + (buf * 2) * B_SEG + col * BSTRIDE_B + seg * 16;
            cp16(smb + so, g_F1h + go);
            cp16(smb + so + B_SEG, g_F1l + go);
        }
        asm volatile("cp.async.commit_group;");
    }

    for (int c = 0; c < 256; ++c) {
        int buf = c & 1;
        if ((c & 3) == 0) {
            #pragma unroll
            for (int t = 0; t < 8; ++t)
                #pragma unroll
                for (int q = 0; q < 4; ++q) acc[t][q] = 0.f;
        }
        if (c < 255) {
            int cn = c + 1;
            int jt = cn >> 2, kcc = (cn & 3) * KC, nbuf = cn & 1;
            for (int i = tid; i < 1024; i += 256) {
                int col = i >> 3, seg = i & 7;
                size_t go = (size_t)(jt * 128 + col) * Dd + kcc + seg * 8;
                uint32_t so = B_OFF + (nbuf * 2) * B_SEG + col * BSTRIDE_B + seg * 16;
                cp16(smb + so, g_F1h + go);
                cp16(smb + so + B_SEG, g_F1l + go);
            }
            asm volatile("cp.async.commit_group;");
            asm volatile("cp.async.wait_group 1;");
        } else {
            asm volatile("cp.async.wait_group 0;");
        }
        __syncthreads();

        int kcc = (c & 3) * KC;
        uint32_t bHiBase = smb + B_OFF + (buf * 2) * B_SEG + bAddrLane;
        uint32_t bLoBase = bHiBase + B_SEG;
        #pragma unroll
        for (int ks = 0; ks < 4; ++ks) {
            unsigned ah[4], al[4];
            uint32_t ak = aAddrBase + (kcc + ks * 16) * 2;
            ldsm4(ah, A_HI_OFF + ak);
            ldsm4(al, A_LO_OFF + ak);
            #pragma unroll
            for (int g = 0; g < 4; ++g) {
                unsigned bh[4], bl[4];
                uint32_t bk = g * 16 * BSTRIDE_B + ks * 32;
                ldsm4(bh, bHiBase + bk);
                ldsm4(bl, bLoBase + bk);
                int t0 = g * 2, t1 = g * 2 + 1;
                mma16816(acc[t0], ah, bh[0], bh[2]);
                mma16816(acc[t0], ah, bl[0], bl[2]);
                mma16816(acc[t0], al, bh[0], bh[2]);
                mma16816(acc[t1], ah, bh[1], bh[3]);
                mma16816(acc[t1], ah, bl[1], bl[3]);
                mma16816(acc[t1], al, bh[1], bh[3]);
            }
        }

        if ((c & 3) == 3) {
            // epilogue for col tile jt = c>>2: insert into per-row top-5
            int jt = c >> 2;
            int j00 = jt * 128 + warp_n * 64 + (lane & 3) * 2;
            #pragma unroll
            for (int t = 0; t < 8; ++t) {
                #pragma unroll
                for (int e = 0; e < 2; ++e) {
                    int j = j00 + t * 8 + e;
                    #pragma unroll
                    for (int r = 0; r < 2; ++r) {
                        float d = acc[t][r * 2 + e];
                        if (d > dv[r][4]) {
                            dv[r][4] = d; di[r][4] = j;
                            #pragma unroll
                            for (int m2 = 3; m2 >= 0; --m2) {
                                if (dv[r][m2 + 1] > dv[r][m2]) {
                                    float tv = dv[r][m2]; dv[r][m2] = dv[r][m2 + 1]; dv[r][m2 + 1] = tv;
                                    int ti = di[r][m2]; di[r][m2] = di[r][m2 + 1]; di[r][m2 + 1] = ti;
                                }
                            }
                        }
                    }
                }
            }
        }
        __syncthreads();
    }

    // ---- merge: 8 lists per row (2 warps x 4 lanes) via smem overlay ----
    float* mval = (float*)sm;                    // [64][40]
    int*   midx = (int*)(sm + 64 * 40 * 4);      // [64][40]
    int slot = warp_n * 4 + (lane & 3);
    int r1 = warp_m * 16 + (lane >> 2);
    int r2 = r1 + 8;
    #pragma unroll
    for (int q = 0; q < 5; ++q) {
        mval[r1 * 40 + slot * 5 + q] = dv[0][q];
        midx[r1 * 40 + slot * 5 + q] = di[0][q];
        mval[r2 * 40 + slot * 5 + q] = dv[1][q];
        midx[r2 * 40 + slot * 5 + q] = di[1][q];
    }
    __syncthreads();

    if (tid < 64) {
        int m = tid;
        // top-8 by (d desc, idx asc) from 40 candidates
        float wv[8]; int wi[8];
        bool usedp[40];
        for (int p = 0; p < 40; ++p) usedp[p] = false;
        for (int sel = 0; sel < 8; ++sel) {
            float best = -3.0f; int bidx = 0x7fffffff; int bpos = -1;
            for (int p = 0; p < 40; ++p) {
                if (usedp[p]) continue;
                float v = mval[m * 40 + p]; int ix = midx[m * 40 + p];
                if (v > best || (v == best && ix < bidx)) { best = v; bidx = ix; bpos = p; }
            }
            usedp[bpos] = true; wv[sel] = best; wi[sel] = bidx;
        }
        // re-rank in A space with reference comparator (A desc, idx asc)
        float av8[8];
        #pragma unroll
        for (int q = 0; q < 8; ++q) av8[q] = affinity(wv[q]);
        bool used[8] = {false,false,false,false,false,false,false,false};
        float fv[5]; int fi[5];
        #pragma unroll
        for (int sel = 0; sel < 5; ++sel) {
            float best = -1e30f; int bidx = 0x7fffffff; int bpos = -1;
            #pragma unroll
            for (int p = 0; p < 8; ++p) {
                if (!used[p] && (av8[p] > best || (av8[p] == best && wi[p] < bidx))) {
                    best = av8[p]; bidx = wi[p]; bpos = p;
                }
            }
            used[bpos] = true; fv[sel] = best; fi[sel] = bidx;
        }
        // ascending index order (matches jax row-sum order)
        #pragma unroll
        for (int a = 0; a < 4; ++a)
            #pragma unroll
            for (int b2 = 0; b2 < 4 - a; ++b2)
                if (fi[b2] > fi[b2 + 1]) {
                    int ti = fi[b2]; fi[b2] = fi[b2 + 1]; fi[b2 + 1] = ti;
                    float tv = fv[b2]; fv[b2] = fv[b2 + 1]; fv[b2 + 1] = tv;
                }
        float sum = 0.f;
        #pragma unroll
        for (int q = 0; q < 5; ++q) sum += fv[q];
        int gr = rowBase + m;
        #pragma unroll
        for (int q = 0; q < 5; ++q) { g_tval[gr * 5 + q] = fv[q]; g_tidx[gr * 5 + q] = fi[q]; }
        g_dinv[gr] = __fdiv_rn(1.0f, __fsqrt_rn(sum));
    }
}

// ---------------- K6: zero + scatter masked A ----------------
__global__ void writeA(float* __restrict__ Aout) {
    int row = blockIdx.x;
    float4* rp = reinterpret_cast<float4*>(Aout + (size_t)row * Nn);
    float4 z = make_float4(0.f, 0.f, 0.f, 0.f);
    #pragma unroll
    for (int s = 0; s < 8; ++s) rp[threadIdx.x + 256 * s] = z;
    __syncthreads();
    if (threadIdx.x < 5) {
        int j = g_tidx[row * 5 + threadIdx.x];
        Aout[(size_t)row * Nn + j] = g_tval[row * 5 + threadIdx.x];
    }
}

// ---------------- K7: out = A_hat @ Y, LeakyReLU ----------------
__global__ void out_gemm(float* __restrict__ Out) {
    __shared__ float sw[5];
    __shared__ int sj[5];
    int row = blockIdx.x;
    if (threadIdx.x < 5) {
        int j = g_tidx[row * 5 + threadIdx.x];
        sj[threadIdx.x] = j;
        sw[threadIdx.x] = (g_dinv[row] * g_tval[row * 5 + threadIdx.x]) * g_dinv[j];
    }
    __syncthreads();
    int c = threadIdx.x;
    float acc = 0.f;
    #pragma unroll
    for (int q = 0; q < 5; ++q)
        acc += sw[q] * g_Y[(size_t)sj[q] * Dd + c];
    Out[(size_t)row * Dd + c] = (acc >= 0.f) ? acc : 0.01f * acc;
}

// ---------------- launcher ----------------
extern "C" void kernel_launch(void* const* d_in, const int* in_sizes, int n_in,
                              void* d_out, int out_size) {
    (void)in_sizes; (void)n_in;
    const float* H     = (const float*)d_in[0];
    const float* gamma = (const float*)d_in[1];
    const float* beta  = (const float*)d_in[2];
    const float* Wt    = (const float*)d_in[3];
    const float* bt    = (const float*)d_in[4];
    const float* Wo    = (const float*)d_in[5];
    const float* bo    = (const float*)d_in[6];
    float* outp = (float*)d_out;

    cudaFuncSetAttribute(topk_mma, cudaFuncAttributeMaxDynamicSharedMemorySize,
                         SMEM_TOTAL_TOPK);

    bn_partial<<<64, 256>>>(H);
    bn_finish<<<1, 256>>>();
    bn_apply<<<(Nn * Dd) / 256, 256>>>(H, gamma, beta);
    gemm_bias<0><<<dim3(Nn / 64, Dd / 64), 256>>>(Wt, bt);
    gemm_bias<1><<<dim3(Nn / 64, Dd / 64), 256>>>(Wo, bo);
    rownorm<<<Nn / 8, 256>>>();
    split_bf16<<<(Nn * Dd) / 256, 256>>>();
    topk_mma<<<Nn / 64, 256, SMEM_TOTAL_TOPK>>>();

    long long need_both = (long long)Nn * Dd + (long long)Nn * Nn;
    if ((long long)out_size >= need_both)
        writeA<<<Nn, 256>>>(outp + (size_t)Nn * Dd);
    out_gemm<<<Nn, 256>>>(outp);
}